// round 5
// baseline (speedup 1.0000x reference)
#include <cuda_runtime.h>

#define BINS   64
#define NB     (BINS * BINS)
#define BATCH  2
#define NELEM  (192 * 224 * 192)   /* 8,257,536 per batch */
#define N4     (NELEM / 4)
#define EPSF   1e-10f

#define MM_BLOCKS   518            /* x-dim; total 1036 = 7/SM */
#define HIST_BLOCKS 444            /* x-dim; total 888  = 6/SM */

// Scratch. Self-restoring: g_hist/g_hist2 re-zeroed, g_minmax/g_done reset
// by the fused final phase -> deterministic across graph replays.
__device__ unsigned int g_hist [BATCH * NB];  // smem-path accumulator
__device__ unsigned int g_hist2[BATCH * NB];  // L2-RED-path accumulator
__device__ unsigned int g_minmax[8] = {       // [c*2]=min-enc, [c*2+1]=max-enc
    0xFFFFFFFFu, 0u, 0xFFFFFFFFu, 0u,         // combo = arr*2 + b (arr0=fixed)
    0xFFFFFFFFu, 0u, 0xFFFFFFFFu, 0u
};
__device__ unsigned int g_done = 0;

__device__ __forceinline__ unsigned int fenc(float f) {
    unsigned int u = __float_as_uint(f);
    return (u & 0x80000000u) ? ~u : (u | 0x80000000u);
}
__device__ __forceinline__ float fdec(unsigned int e) {
    unsigned int u = (e & 0x80000000u) ? (e & 0x7fffffffu) : ~e;
    return __uint_as_float(u);
}

// Pass 1: forward stream, per-batch min/max of fixed AND warped.
__global__ void __launch_bounds__(256, 7)
minmaxK(const float4* __restrict__ fixedp,
        const float4* __restrict__ warpedp) {
    int b = blockIdx.y;
    const float4* f4 = fixedp  + (size_t)b * N4;
    const float4* w4 = warpedp + (size_t)b * N4;

    float fmn = 3.4e38f, fmx = -3.4e38f, wmn = 3.4e38f, wmx = -3.4e38f;
    for (int i = blockIdx.x * blockDim.x + threadIdx.x; i < N4;
         i += gridDim.x * blockDim.x) {
        float4 f = f4[i];
        float4 w = w4[i];
        fmn = fminf(fmn, fminf(fminf(f.x, f.y), fminf(f.z, f.w)));
        fmx = fmaxf(fmx, fmaxf(fmaxf(f.x, f.y), fmaxf(f.z, f.w)));
        wmn = fminf(wmn, fminf(fminf(w.x, w.y), fminf(w.z, w.w)));
        wmx = fmaxf(wmx, fmaxf(fmaxf(w.x, w.y), fmaxf(w.z, w.w)));
    }
    #pragma unroll
    for (int o = 16; o; o >>= 1) {
        fmn = fminf(fmn, __shfl_down_sync(0xFFFFFFFFu, fmn, o));
        fmx = fmaxf(fmx, __shfl_down_sync(0xFFFFFFFFu, fmx, o));
        wmn = fminf(wmn, __shfl_down_sync(0xFFFFFFFFu, wmn, o));
        wmx = fmaxf(wmx, __shfl_down_sync(0xFFFFFFFFu, wmx, o));
    }
    __shared__ float s0[8], s1[8], s2[8], s3[8];
    int w = threadIdx.x >> 5, l = threadIdx.x & 31;
    if (l == 0) { s0[w] = fmn; s1[w] = fmx; s2[w] = wmn; s3[w] = wmx; }
    __syncthreads();
    if (threadIdx.x == 0) {
        float a = s0[0], bb = s1[0], c = s2[0], d = s3[0];
        #pragma unroll
        for (int k = 1; k < 8; k++) {
            a = fminf(a, s0[k]); bb = fmaxf(bb, s1[k]);
            c = fminf(c, s2[k]); d = fmaxf(d, s3[k]);
        }
        atomicMin(&g_minmax[(0 * 2 + b) * 2 + 0], fenc(a));
        atomicMax(&g_minmax[(0 * 2 + b) * 2 + 1], fenc(bb));
        atomicMin(&g_minmax[(1 * 2 + b) * 2 + 0], fenc(c));
        atomicMax(&g_minmax[(1 * 2 + b) * 2 + 1], fenc(d));
    }
}

__device__ __forceinline__ int binof(float x, float s, float c) {
    return min(max(__float2int_rz(fmaf(x, s, c)), 0), BINS - 1);
}

// Pass 2 (REVERSE stream, L2-reuse of pass-1 tail) + fused final reduction.
// Atomic load split across two independent ALUs: elements .x/.y -> block-
// private SMEM histogram (L1 atomic unit), .z/.w -> global g_hist2 (L2/LTS
// RED unit). The two pipes run in parallel; each sees half of 16.5M ops.
__global__ void __launch_bounds__(256, 6)
histK(const float* __restrict__ fixedp,
      const float* __restrict__ warpedp,
      const float* __restrict__ pred,
      const float* __restrict__ tru,
      float* __restrict__ out) {
    int b = blockIdx.y;
    __shared__ unsigned int sh[NB];
    __shared__ float red[8];
    __shared__ float hmarg[2];
    __shared__ unsigned int s_last;
    int t = threadIdx.x;
    int w = t >> 5, l = t & 31;

    for (int i = t; i < NB; i += blockDim.x) sh[i] = 0u;
    __syncthreads();

    float fmn = fdec(g_minmax[(0 * 2 + b) * 2 + 0]);
    float fmx = fdec(g_minmax[(0 * 2 + b) * 2 + 1]);
    float wmn = fdec(g_minmax[(1 * 2 + b) * 2 + 0]);
    float wmx = fdec(g_minmax[(1 * 2 + b) * 2 + 1]);
    float fs = (float)(BINS - 1) / (fmx - fmn + EPSF);
    float ws = (float)(BINS - 1) / (wmx - wmn + EPSF);
    float fc = -fmn * fs;   // bin = x*fs + fc  (one FFMA)
    float wc = -wmn * ws;

    const float4* f4 = (const float4*)(fixedp + (size_t)b * NELEM);
    const float4* w4 = (const float4*)(warpedp + (size_t)b * NELEM);
    unsigned int* g2 = g_hist2 + b * NB;

    for (int i = blockIdx.x * blockDim.x + t; i < N4;
         i += gridDim.x * blockDim.x) {
        int j = (N4 - 1) - i;          // reverse traversal for L2 reuse
        float4 f = f4[j];
        float4 wv = w4[j];
        // .x/.y -> SMEM atomic pipe
        atomicAdd(&sh[binof(f.x, fs, fc) * BINS + binof(wv.x, ws, wc)], 1u);
        atomicAdd(&sh[binof(f.y, fs, fc) * BINS + binof(wv.y, ws, wc)], 1u);
        // .z/.w -> L2 RED pipe (no return -> REDG)
        atomicAdd(&g2[binof(f.z, fs, fc) * BINS + binof(wv.z, ws, wc)], 1u);
        atomicAdd(&g2[binof(f.w, fs, fc) * BINS + binof(wv.w, ws, wc)], 1u);
    }
    __syncthreads();

    // Flush smem histogram as packed u64 (low half can't carry into high).
    unsigned long long* gh64 = (unsigned long long*)(g_hist + b * NB);
    const unsigned long long* sh64 = (const unsigned long long*)sh;
    for (int i = t; i < NB / 2; i += blockDim.x) {
        unsigned long long v = sh64[i];
        if (v) atomicAdd(&gh64[i], v);
    }
    __threadfence();
    __syncthreads();

    // Last-block-does-final.
    if (t == 0) {
        unsigned int total = gridDim.x * gridDim.y;
        unsigned int old = atomicAdd(&g_done, 1u);
        s_last = (old == total - 1) ? 1u : 0u;
    }
    __syncthreads();
    if (!s_last) return;

    __threadfence();
    float* shf = (float*)sh;
    const float invN = 1.0f / ((float)NELEM + EPSF);
    float nmi_sum = 0.f;

    for (int bb = 0; bb < BATCH; bb++) {
        unsigned int* gh  = g_hist  + bb * NB;
        unsigned int* gh2 = g_hist2 + bb * NB;
        if (t < 2) hmarg[t] = 0.f;

        float hj = 0.f;
        #pragma unroll
        for (int k = 0; k < NB / 256; k++) {
            int i = t + k * 256;
            float c = (float)(__ldcg(&gh[i]) + __ldcg(&gh2[i]));
            gh[i] = 0u;   gh2[i] = 0u;        // self-restore
            shf[i] = c;
            float p = c * invN;
            hj -= p * __logf(p + EPSF);
        }
        #pragma unroll
        for (int o = 16; o; o >>= 1) hj += __shfl_down_sync(0xFFFFFFFFu, hj, o);
        if (l == 0) red[w] = hj;
        __syncthreads();

        float hterm = 0.f;
        if (t < 64) {
            float rs = 0.f;
            #pragma unroll
            for (int j = 0; j < BINS; j++) rs += shf[t * BINS + ((j + t) & 63)];
            float p = rs * invN;
            hterm = -p * __logf(p + EPSF);
        } else if (t < 128) {
            int c = t - 64;
            float cs = 0.f;
            #pragma unroll
            for (int j = 0; j < BINS; j++) cs += shf[j * BINS + c];
            float p = cs * invN;
            hterm = -p * __logf(p + EPSF);
        }
        #pragma unroll
        for (int o = 16; o; o >>= 1)
            hterm += __shfl_down_sync(0xFFFFFFFFu, hterm, o);
        if (l == 0 && w < 4) atomicAdd(&hmarg[w >> 1], hterm);
        __syncthreads();

        float h_j = 0.f;
        #pragma unroll
        for (int k = 0; k < 8; k++) h_j += red[k];
        float h_f = hmarg[0], h_w = hmarg[1];
        nmi_sum += 2.f * (h_f + h_w - h_j) / (h_f + h_w + EPSF);
        __syncthreads();
    }

    if (t == 0) {
        #pragma unroll
        for (int k = 0; k < 4; k++) {
            g_minmax[k * 2 + 0] = 0xFFFFFFFFu;
            g_minmax[k * 2 + 1] = 0u;
        }
        g_done = 0u;
        float mse = 0.f;
        #pragma unroll
        for (int i = 0; i < BATCH * 12; i++) {
            float d = pred[i] - tru[i];
            mse += d * d;
        }
        mse /= (float)(BATCH * 12);
        out[0] = mse - nmi_sum / (float)BATCH;
        __threadfence();
    }
}

extern "C" void kernel_launch(void* const* d_in, const int* in_sizes, int n_in,
                              void* d_out, int out_size) {
    const float* pred    = (const float*)d_in[0];
    const float* tru     = (const float*)d_in[1];
    const float* fixedp  = (const float*)d_in[2];
    const float* warpedp = (const float*)d_in[3];

    dim3 g1(MM_BLOCKS, BATCH);
    minmaxK<<<g1, 256>>>((const float4*)fixedp, (const float4*)warpedp);

    dim3 g2(HIST_BLOCKS, BATCH);
    histK<<<g2, 256>>>(fixedp, warpedp, pred, tru, (float*)d_out);
}

// round 6
// speedup vs baseline: 4.2769x; 4.2769x over previous
#include <cuda_runtime.h>

#define BINS   64
#define NB     (BINS * BINS)
#define BATCH  2
#define NELEM  (192 * 224 * 192)   /* 8,257,536 per batch */
#define N4     (NELEM / 4)
#define EPSF   1e-10f

#define MM_BLOCKS   518            /* x-dim; total 1036 = 7/SM */
#define HIST_BLOCKS 444            /* x-dim; total 888  = 6/SM */

// Scratch. Self-restoring: g_hist re-zeroed, g_minmax/g_done reset by the
// fused final phase -> deterministic across graph replays.
__device__ unsigned int g_hist[BATCH * NB];   // static-zeroed
__device__ unsigned int g_minmax[8] = {       // [c*2]=min-enc, [c*2+1]=max-enc
    0xFFFFFFFFu, 0u, 0xFFFFFFFFu, 0u,         // combo = arr*2 + b (arr0=fixed)
    0xFFFFFFFFu, 0u, 0xFFFFFFFFu, 0u
};
__device__ unsigned int g_done = 0;

__device__ __forceinline__ unsigned int fenc(float f) {
    unsigned int u = __float_as_uint(f);
    return (u & 0x80000000u) ? ~u : (u | 0x80000000u);
}
__device__ __forceinline__ float fdec(unsigned int e) {
    unsigned int u = (e & 0x80000000u) ? (e & 0x7fffffffu) : ~e;
    return __uint_as_float(u);
}

// Pass 1: REVERSE stream. Reads tail-first (tail is L2-resident from the
// previous replay's forward histK) and finishes at the array heads, leaving
// them resident for histK's forward pass right after. The reversal cost
// lands here, on a pure streaming reduction, not on the atomic-bound hist.
__global__ void __launch_bounds__(256, 7)
minmaxK(const float4* __restrict__ fixedp,
        const float4* __restrict__ warpedp) {
    int b = blockIdx.y;
    const float4* f4 = fixedp  + (size_t)b * N4;
    const float4* w4 = warpedp + (size_t)b * N4;

    float fmn = 3.4e38f, fmx = -3.4e38f, wmn = 3.4e38f, wmx = -3.4e38f;
    for (int i = blockIdx.x * blockDim.x + threadIdx.x; i < N4;
         i += gridDim.x * blockDim.x) {
        int j = (N4 - 1) - i;          // reverse traversal
        float4 f = f4[j];
        float4 w = w4[j];
        fmn = fminf(fmn, fminf(fminf(f.x, f.y), fminf(f.z, f.w)));
        fmx = fmaxf(fmx, fmaxf(fmaxf(f.x, f.y), fmaxf(f.z, f.w)));
        wmn = fminf(wmn, fminf(fminf(w.x, w.y), fminf(w.z, w.w)));
        wmx = fmaxf(wmx, fmaxf(fmaxf(w.x, w.y), fmaxf(w.z, w.w)));
    }
    #pragma unroll
    for (int o = 16; o; o >>= 1) {
        fmn = fminf(fmn, __shfl_down_sync(0xFFFFFFFFu, fmn, o));
        fmx = fmaxf(fmx, __shfl_down_sync(0xFFFFFFFFu, fmx, o));
        wmn = fminf(wmn, __shfl_down_sync(0xFFFFFFFFu, wmn, o));
        wmx = fmaxf(wmx, __shfl_down_sync(0xFFFFFFFFu, wmx, o));
    }
    __shared__ float s0[8], s1[8], s2[8], s3[8];
    int w = threadIdx.x >> 5, l = threadIdx.x & 31;
    if (l == 0) { s0[w] = fmn; s1[w] = fmx; s2[w] = wmn; s3[w] = wmx; }
    __syncthreads();
    if (threadIdx.x == 0) {
        float a = s0[0], bb = s1[0], c = s2[0], d = s3[0];
        #pragma unroll
        for (int k = 1; k < 8; k++) {
            a = fminf(a, s0[k]); bb = fmaxf(bb, s1[k]);
            c = fminf(c, s2[k]); d = fmaxf(d, s3[k]);
        }
        atomicMin(&g_minmax[(0 * 2 + b) * 2 + 0], fenc(a));
        atomicMax(&g_minmax[(0 * 2 + b) * 2 + 1], fenc(bb));
        atomicMin(&g_minmax[(1 * 2 + b) * 2 + 0], fenc(c));
        atomicMax(&g_minmax[(1 * 2 + b) * 2 + 1], fenc(d));
    }
}

__device__ __forceinline__ int binof(float x, float s, float c) {
    return min(max(__float2int_rz(fmaf(x, s, c)), 0), BINS - 1);
}

// Pass 2: FORWARD stream (heads L2-resident from minmaxK's reverse pass;
// leaves tails resident for the next replay's minmaxK). All atomics go to
// the block-private SMEM histogram — R5 proved the L2-RED path is ~7x
// slower at this bin-reuse density. Fused final reduction (saves a launch).
__global__ void __launch_bounds__(256, 6)
histK(const float* __restrict__ fixedp,
      const float* __restrict__ warpedp,
      const float* __restrict__ pred,
      const float* __restrict__ tru,
      float* __restrict__ out) {
    int b = blockIdx.y;
    __shared__ unsigned int sh[NB];
    __shared__ float red[8];
    __shared__ float hmarg[2];
    __shared__ unsigned int s_last;
    int t = threadIdx.x;
    int w = t >> 5, l = t & 31;

    for (int i = t; i < NB; i += blockDim.x) sh[i] = 0u;
    __syncthreads();

    float fmn = fdec(g_minmax[(0 * 2 + b) * 2 + 0]);
    float fmx = fdec(g_minmax[(0 * 2 + b) * 2 + 1]);
    float wmn = fdec(g_minmax[(1 * 2 + b) * 2 + 0]);
    float wmx = fdec(g_minmax[(1 * 2 + b) * 2 + 1]);
    float fs = (float)(BINS - 1) / (fmx - fmn + EPSF);
    float ws = (float)(BINS - 1) / (wmx - wmn + EPSF);
    float fc = -fmn * fs;   // bin = x*fs + fc  (one FFMA)
    float wc = -wmn * ws;

    const float4* f4 = (const float4*)(fixedp + (size_t)b * NELEM);
    const float4* w4 = (const float4*)(warpedp + (size_t)b * NELEM);

    for (int i = blockIdx.x * blockDim.x + t; i < N4;
         i += gridDim.x * blockDim.x) {
        float4 f = f4[i];
        float4 wv = w4[i];
        atomicAdd(&sh[binof(f.x, fs, fc) * BINS + binof(wv.x, ws, wc)], 1u);
        atomicAdd(&sh[binof(f.y, fs, fc) * BINS + binof(wv.y, ws, wc)], 1u);
        atomicAdd(&sh[binof(f.z, fs, fc) * BINS + binof(wv.z, ws, wc)], 1u);
        atomicAdd(&sh[binof(f.w, fs, fc) * BINS + binof(wv.w, ws, wc)], 1u);
    }
    __syncthreads();

    // Flush as packed u64 (low half can't carry into high: counts << 2^32).
    unsigned long long* gh64 = (unsigned long long*)(g_hist + b * NB);
    const unsigned long long* sh64 = (const unsigned long long*)sh;
    for (int i = t; i < NB / 2; i += blockDim.x) {
        unsigned long long v = sh64[i];
        if (v) atomicAdd(&gh64[i], v);
    }
    __threadfence();
    __syncthreads();

    // Last-block-does-final.
    if (t == 0) {
        unsigned int total = gridDim.x * gridDim.y;
        unsigned int old = atomicAdd(&g_done, 1u);
        s_last = (old == total - 1) ? 1u : 0u;
    }
    __syncthreads();
    if (!s_last) return;

    __threadfence();
    float* shf = (float*)sh;
    const float invN = 1.0f / ((float)NELEM + EPSF);
    float nmi_sum = 0.f;

    for (int bb = 0; bb < BATCH; bb++) {
        unsigned int* gh = g_hist + bb * NB;
        if (t < 2) hmarg[t] = 0.f;

        float hj = 0.f;
        #pragma unroll
        for (int k = 0; k < NB / 256; k++) {
            int i = t + k * 256;
            float c = (float)__ldcg(&gh[i]);
            gh[i] = 0u;              // self-restore
            shf[i] = c;
            float p = c * invN;
            hj -= p * __logf(p + EPSF);
        }
        #pragma unroll
        for (int o = 16; o; o >>= 1) hj += __shfl_down_sync(0xFFFFFFFFu, hj, o);
        if (l == 0) red[w] = hj;
        __syncthreads();

        float hterm = 0.f;
        if (t < 64) {
            float rs = 0.f;
            #pragma unroll
            for (int j = 0; j < BINS; j++) rs += shf[t * BINS + ((j + t) & 63)];
            float p = rs * invN;
            hterm = -p * __logf(p + EPSF);
        } else if (t < 128) {
            int c = t - 64;
            float cs = 0.f;
            #pragma unroll
            for (int j = 0; j < BINS; j++) cs += shf[j * BINS + c];
            float p = cs * invN;
            hterm = -p * __logf(p + EPSF);
        }
        #pragma unroll
        for (int o = 16; o; o >>= 1)
            hterm += __shfl_down_sync(0xFFFFFFFFu, hterm, o);
        if (l == 0 && w < 4) atomicAdd(&hmarg[w >> 1], hterm);
        __syncthreads();

        float h_j = 0.f;
        #pragma unroll
        for (int k = 0; k < 8; k++) h_j += red[k];
        float h_f = hmarg[0], h_w = hmarg[1];
        nmi_sum += 2.f * (h_f + h_w - h_j) / (h_f + h_w + EPSF);
        __syncthreads();
    }

    if (t == 0) {
        #pragma unroll
        for (int k = 0; k < 4; k++) {
            g_minmax[k * 2 + 0] = 0xFFFFFFFFu;
            g_minmax[k * 2 + 1] = 0u;
        }
        g_done = 0u;
        float mse = 0.f;
        #pragma unroll
        for (int i = 0; i < BATCH * 12; i++) {
            float d = pred[i] - tru[i];
            mse += d * d;
        }
        mse /= (float)(BATCH * 12);
        out[0] = mse - nmi_sum / (float)BATCH;
        __threadfence();
    }
}

extern "C" void kernel_launch(void* const* d_in, const int* in_sizes, int n_in,
                              void* d_out, int out_size) {
    const float* pred    = (const float*)d_in[0];
    const float* tru     = (const float*)d_in[1];
    const float* fixedp  = (const float*)d_in[2];
    const float* warpedp = (const float*)d_in[3];

    dim3 g1(MM_BLOCKS, BATCH);
    minmaxK<<<g1, 256>>>((const float4*)fixedp, (const float4*)warpedp);

    dim3 g2(HIST_BLOCKS, BATCH);
    histK<<<g2, 256>>>(fixedp, warpedp, pred, tru, (float*)d_out);
}

// round 7
// speedup vs baseline: 4.6854x; 1.0955x over previous
#include <cuda_runtime.h>

#define BINS   64
#define NB     (BINS * BINS)
#define BATCH  2
#define NELEM  (192 * 224 * 192)   /* 8,257,536 per batch */
#define N4     (NELEM / 4)
#define EPSF   1e-10f

#define MM_BLOCKS   518            /* x-dim; total 1036 = 7/SM @256thr */
#define HIST_BLOCKS 222            /* x-dim; total 444  = 3/SM @512thr */
#define HTHREADS    512

// Scratch. Self-restoring: g_hist re-zeroed, g_minmax/g_done reset by the
// fused final phase -> deterministic across graph replays.
__device__ unsigned int g_hist[BATCH * NB];   // static-zeroed
__device__ unsigned int g_minmax[8] = {       // [c*2]=min-enc, [c*2+1]=max-enc
    0xFFFFFFFFu, 0u, 0xFFFFFFFFu, 0u,         // combo = arr*2 + b (arr0=fixed)
    0xFFFFFFFFu, 0u, 0xFFFFFFFFu, 0u
};
__device__ unsigned int g_done = 0;

__device__ __forceinline__ unsigned int fenc(float f) {
    unsigned int u = __float_as_uint(f);
    return (u & 0x80000000u) ? ~u : (u | 0x80000000u);
}
__device__ __forceinline__ float fdec(unsigned int e) {
    unsigned int u = (e & 0x80000000u) ? (e & 0x7fffffffu) : ~e;
    return __uint_as_float(u);
}

// Pass 1: REVERSE stream (tail L2-resident from previous replay's forward
// histK); finishes at heads, leaving them resident for histK right after.
__global__ void __launch_bounds__(256, 7)
minmaxK(const float4* __restrict__ fixedp,
        const float4* __restrict__ warpedp) {
    int b = blockIdx.y;
    const float4* f4 = fixedp  + (size_t)b * N4;
    const float4* w4 = warpedp + (size_t)b * N4;

    float fmn = 3.4e38f, fmx = -3.4e38f, wmn = 3.4e38f, wmx = -3.4e38f;
    for (int i = blockIdx.x * blockDim.x + threadIdx.x; i < N4;
         i += gridDim.x * blockDim.x) {
        int j = (N4 - 1) - i;          // reverse traversal
        float4 f = f4[j];
        float4 w = w4[j];
        fmn = fminf(fmn, fminf(fminf(f.x, f.y), fminf(f.z, f.w)));
        fmx = fmaxf(fmx, fmaxf(fmaxf(f.x, f.y), fmaxf(f.z, f.w)));
        wmn = fminf(wmn, fminf(fminf(w.x, w.y), fminf(w.z, w.w)));
        wmx = fmaxf(wmx, fmaxf(fmaxf(w.x, w.y), fmaxf(w.z, w.w)));
    }
    #pragma unroll
    for (int o = 16; o; o >>= 1) {
        fmn = fminf(fmn, __shfl_down_sync(0xFFFFFFFFu, fmn, o));
        fmx = fmaxf(fmx, __shfl_down_sync(0xFFFFFFFFu, fmx, o));
        wmn = fminf(wmn, __shfl_down_sync(0xFFFFFFFFu, wmn, o));
        wmx = fmaxf(wmx, __shfl_down_sync(0xFFFFFFFFu, wmx, o));
    }
    __shared__ float s0[8], s1[8], s2[8], s3[8];
    int w = threadIdx.x >> 5, l = threadIdx.x & 31;
    if (l == 0) { s0[w] = fmn; s1[w] = fmx; s2[w] = wmn; s3[w] = wmx; }
    __syncthreads();
    if (threadIdx.x == 0) {
        float a = s0[0], bb = s1[0], c = s2[0], d = s3[0];
        #pragma unroll
        for (int k = 1; k < 8; k++) {
            a = fminf(a, s0[k]); bb = fmaxf(bb, s1[k]);
            c = fminf(c, s2[k]); d = fmaxf(d, s3[k]);
        }
        atomicMin(&g_minmax[(0 * 2 + b) * 2 + 0], fenc(a));
        atomicMax(&g_minmax[(0 * 2 + b) * 2 + 1], fenc(bb));
        atomicMin(&g_minmax[(1 * 2 + b) * 2 + 0], fenc(c));
        atomicMax(&g_minmax[(1 * 2 + b) * 2 + 1], fenc(d));
    }
}

__device__ __forceinline__ int binof(float x, float s, float c) {
    return min(max(__float2int_rz(fmaf(x, s, c)), 0), BINS - 1);
}

// Pass 2: FORWARD stream, all-SMEM atomics (at hardware ATOMS floor; R5
// proved L2-RED is 7x worse here). 512 threads x 3 blocks/SM: same warp
// count/occupancy as 256x6, but HALF the private histograms -> half the
// global flush REDG (0.91M instead of 1.82M onto 8192 hot L2 lines).
__global__ void __launch_bounds__(HTHREADS, 3)
histK(const float* __restrict__ fixedp,
      const float* __restrict__ warpedp,
      const float* __restrict__ pred,
      const float* __restrict__ tru,
      float* __restrict__ out) {
    int b = blockIdx.y;
    __shared__ unsigned int sh[NB];
    __shared__ float red[16];
    __shared__ float hmarg[2];
    __shared__ unsigned int s_last;
    int t = threadIdx.x;
    int w = t >> 5, l = t & 31;

    for (int i = t; i < NB; i += HTHREADS) sh[i] = 0u;
    __syncthreads();

    float fmn = fdec(g_minmax[(0 * 2 + b) * 2 + 0]);
    float fmx = fdec(g_minmax[(0 * 2 + b) * 2 + 1]);
    float wmn = fdec(g_minmax[(1 * 2 + b) * 2 + 0]);
    float wmx = fdec(g_minmax[(1 * 2 + b) * 2 + 1]);
    float fs = (float)(BINS - 1) / (fmx - fmn + EPSF);
    float ws = (float)(BINS - 1) / (wmx - wmn + EPSF);
    float fc = -fmn * fs;   // bin = x*fs + fc  (one FFMA)
    float wc = -wmn * ws;

    const float4* f4 = (const float4*)(fixedp + (size_t)b * NELEM);
    const float4* w4 = (const float4*)(warpedp + (size_t)b * NELEM);

    for (int i = blockIdx.x * HTHREADS + t; i < N4;
         i += gridDim.x * HTHREADS) {
        float4 f = f4[i];
        float4 wv = w4[i];
        atomicAdd(&sh[binof(f.x, fs, fc) * BINS + binof(wv.x, ws, wc)], 1u);
        atomicAdd(&sh[binof(f.y, fs, fc) * BINS + binof(wv.y, ws, wc)], 1u);
        atomicAdd(&sh[binof(f.z, fs, fc) * BINS + binof(wv.z, ws, wc)], 1u);
        atomicAdd(&sh[binof(f.w, fs, fc) * BINS + binof(wv.w, ws, wc)], 1u);
    }
    __syncthreads();

    // Flush as packed u64 (low half can't carry into high: counts << 2^32).
    unsigned long long* gh64 = (unsigned long long*)(g_hist + b * NB);
    const unsigned long long* sh64 = (const unsigned long long*)sh;
    for (int i = t; i < NB / 2; i += HTHREADS) {
        unsigned long long v = sh64[i];
        if (v) atomicAdd(&gh64[i], v);
    }
    __threadfence();
    __syncthreads();

    // Last-block-does-final.
    if (t == 0) {
        unsigned int total = gridDim.x * gridDim.y;
        unsigned int old = atomicAdd(&g_done, 1u);
        s_last = (old == total - 1) ? 1u : 0u;
    }
    __syncthreads();
    if (!s_last) return;

    __threadfence();
    float* shf = (float*)sh;
    const float invN = 1.0f / ((float)NELEM + EPSF);
    float nmi_sum = 0.f;

    for (int bb = 0; bb < BATCH; bb++) {
        unsigned int* gh = g_hist + bb * NB;
        if (t < 2) hmarg[t] = 0.f;

        float hj = 0.f;
        #pragma unroll
        for (int k = 0; k < NB / HTHREADS; k++) {
            int i = t + k * HTHREADS;
            float c = (float)__ldcg(&gh[i]);
            gh[i] = 0u;              // self-restore
            shf[i] = c;
            float p = c * invN;
            hj -= p * __logf(p + EPSF);
        }
        #pragma unroll
        for (int o = 16; o; o >>= 1) hj += __shfl_down_sync(0xFFFFFFFFu, hj, o);
        if (l == 0) red[w] = hj;
        __syncthreads();

        float hterm = 0.f;
        if (t < 64) {
            float rs = 0.f;
            #pragma unroll
            for (int j = 0; j < BINS; j++) rs += shf[t * BINS + ((j + t) & 63)];
            float p = rs * invN;
            hterm = -p * __logf(p + EPSF);
        } else if (t < 128) {
            int c = t - 64;
            float cs = 0.f;
            #pragma unroll
            for (int j = 0; j < BINS; j++) cs += shf[j * BINS + c];
            float p = cs * invN;
            hterm = -p * __logf(p + EPSF);
        }
        #pragma unroll
        for (int o = 16; o; o >>= 1)
            hterm += __shfl_down_sync(0xFFFFFFFFu, hterm, o);
        if (l == 0 && w < 4) atomicAdd(&hmarg[w >> 1], hterm);
        __syncthreads();

        float h_j = 0.f;
        #pragma unroll
        for (int k = 0; k < 16; k++) h_j += red[k];
        float h_f = hmarg[0], h_w = hmarg[1];
        nmi_sum += 2.f * (h_f + h_w - h_j) / (h_f + h_w + EPSF);
        __syncthreads();
    }

    if (t == 0) {
        #pragma unroll
        for (int k = 0; k < 4; k++) {
            g_minmax[k * 2 + 0] = 0xFFFFFFFFu;
            g_minmax[k * 2 + 1] = 0u;
        }
        g_done = 0u;
        float mse = 0.f;
        #pragma unroll
        for (int i = 0; i < BATCH * 12; i++) {
            float d = pred[i] - tru[i];
            mse += d * d;
        }
        mse /= (float)(BATCH * 12);
        out[0] = mse - nmi_sum / (float)BATCH;
        __threadfence();
    }
}

extern "C" void kernel_launch(void* const* d_in, const int* in_sizes, int n_in,
                              void* d_out, int out_size) {
    const float* pred    = (const float*)d_in[0];
    const float* tru     = (const float*)d_in[1];
    const float* fixedp  = (const float*)d_in[2];
    const float* warpedp = (const float*)d_in[3];

    dim3 g1(MM_BLOCKS, BATCH);
    minmaxK<<<g1, 256>>>((const float4*)fixedp, (const float4*)warpedp);

    dim3 g2(HIST_BLOCKS, BATCH);
    histK<<<g2, HTHREADS>>>(fixedp, warpedp, pred, tru, (float*)d_out);
}